// round 9
// baseline (speedup 1.0000x reference)
#include <cuda_runtime.h>
#include <cuda_bf16.h>
#include <cstdint>
#include <cstddef>

#define NN 50000
#define EE 250000
#define LL 4
#define LN_EPS 1e-5f
#define RS 272   // padded smem row stride in bytes (136 bf16)
#define TM 64    // rows per CTA tile

// ---------------------------------------------------------------------------
// device scratch
// ---------------------------------------------------------------------------
__device__ float g_agg[(size_t)NN * 128];
__device__ float g_XA[(size_t)NN * 128];   // x@eW1a + eb1
__device__ float g_XB[(size_t)NN * 128];   // x@eW1b
// weight images: [layer][mat(7)][hi/lo] each 128x128 bf16, stored as W^T[n][k]
// mats: 0=eW1a 1=eW1b 2=eW1c 3=eW2 4=nW1a 5=nW1b 6=nW2
__device__ __nv_bfloat16 g_wimg[(size_t)4 * 7 * 2 * 16384];

// ---------------------------------------------------------------------------
// shared memory  (~107 KB -> 2 CTAs/SM)
// ---------------------------------------------------------------------------
struct SmemT {
    union {
        __nv_bfloat16 Atiles[2 * TM * 136];  // A_hi then A_lo
        float OT[TM * 132];                  // staged output tile
    };
    __nv_bfloat16 W_hi[128 * 136];
    __nv_bfloat16 W_lo[128 * 136];
    float part_s[TM][4];
    float part_s2[TM][4];
    int idx0[TM];   // edge src (x_j + scatter target)
    int idx1[TM];   // edge dst (x_i)
};

// ---------------------------------------------------------------------------
// PTX helpers
// ---------------------------------------------------------------------------
__device__ __forceinline__ uint32_t smem_u32(const void* p) {
    uint32_t a;
    asm("{ .reg .u64 t; cvta.to.shared.u64 t, %1; cvt.u32.u64 %0, t; }" : "=r"(a) : "l"(p));
    return a;
}
__device__ __forceinline__ void ldm4(uint32_t r[4], uint32_t a) {
    asm volatile("ldmatrix.sync.aligned.m8n8.x4.shared.b16 {%0,%1,%2,%3}, [%4];"
        : "=r"(r[0]), "=r"(r[1]), "=r"(r[2]), "=r"(r[3]) : "r"(a));
}
__device__ __forceinline__ void mma16816(float c[4], const uint32_t a[4], uint32_t b0, uint32_t b1) {
    asm volatile("mma.sync.aligned.m16n8k16.row.col.f32.bf16.bf16.f32 "
        "{%0,%1,%2,%3},{%4,%5,%6,%7},{%8,%9},{%0,%1,%2,%3};"
        : "+f"(c[0]), "+f"(c[1]), "+f"(c[2]), "+f"(c[3])
        : "r"(a[0]), "r"(a[1]), "r"(a[2]), "r"(a[3]), "r"(b0), "r"(b1));
}
__device__ __forceinline__ void cp16(uint32_t dst, const void* src) {
    asm volatile("cp.async.cg.shared.global [%0], [%1], 16;" :: "r"(dst), "l"(src));
}
#define CP_COMMIT_WAIT() asm volatile("cp.async.commit_group;\n\tcp.async.wait_group 0;" ::: "memory")

// split fp32 pair -> bf16 hi/lo (c even)
__device__ __forceinline__ void store_pair(char* hi, char* lo, int r, int c, float v0, float v1) {
    int off = r * RS + c * 2;
    __nv_bfloat16 h0 = __float2bfloat16(v0), h1 = __float2bfloat16(v1);
    __nv_bfloat16 l0 = __float2bfloat16(v0 - __bfloat162float(h0));
    __nv_bfloat16 l1 = __float2bfloat16(v1 - __bfloat162float(h1));
    *(__nv_bfloat162*)(hi + off) = __halves2bfloat162(h0, h1);
    *(__nv_bfloat162*)(lo + off) = __halves2bfloat162(l0, l1);
}

// split fp32 quad -> bf16 hi/lo as single 8B stores (c multiple of 4)
__device__ __forceinline__ void store_quad(char* hi, char* lo, int r, int c, float4 v) {
    int off = r * RS + c * 2;
    __nv_bfloat16 h0 = __float2bfloat16(v.x), h1 = __float2bfloat16(v.y);
    __nv_bfloat16 h2 = __float2bfloat16(v.z), h3 = __float2bfloat16(v.w);
    __nv_bfloat16 l0 = __float2bfloat16(v.x - __bfloat162float(h0));
    __nv_bfloat16 l1 = __float2bfloat16(v.y - __bfloat162float(h1));
    __nv_bfloat16 l2 = __float2bfloat16(v.z - __bfloat162float(h2));
    __nv_bfloat16 l3 = __float2bfloat16(v.w - __bfloat162float(h3));
    __nv_bfloat162 hp[2] = { __halves2bfloat162(h0, h1), __halves2bfloat162(h2, h3) };
    __nv_bfloat162 lp[2] = { __halves2bfloat162(l0, l1), __halves2bfloat162(l2, l3) };
    *(uint2*)(hi + off) = *(const uint2*)hp;
    *(uint2*)(lo + off) = *(const uint2*)lp;
}

// copy one hi/lo weight image pair into padded smem tiles via cp.async
__device__ __forceinline__ void copy_w(int layer, int mat, uint32_t whi, uint32_t wlo, int tid) {
    size_t base = (size_t)((layer * 7 + mat) * 2) * 16384;
    const uint4* sh = (const uint4*)(g_wimg + base);
    const uint4* sl = (const uint4*)(g_wimg + base + 16384);
    for (int i = tid; i < 2048; i += 512) {
        int row = i >> 4, q = i & 15;
        cp16(whi + row * RS + q * 16, sh + i);
        cp16(wlo + row * RS + q * 16, sl + i);
    }
}

// ---------------------------------------------------------------------------
// 64x128x128 bf16x3 GEMM, 16 warps in 4x4 grid.
// ---------------------------------------------------------------------------
__device__ __forceinline__ void gemm_bf16x3(
    float acc[4][4], uint32_t aHi, uint32_t aLo, uint32_t wHi, uint32_t wLo,
    int lane, int wm, int wn)
{
    const uint32_t aoff = (uint32_t)((wm * 16 + (lane & 15)) * RS + (lane >> 4) * 16);
    const uint32_t boff = (uint32_t)((wn * 32 + (lane & 7) + ((lane >> 4) & 1) * 8) * RS
                                     + ((lane >> 3) & 1) * 16);
#pragma unroll
    for (int ks = 0; ks < 8; ks++) {
        const uint32_t ka = aoff + ks * 32;
        const uint32_t kb = boff + ks * 32;
        uint32_t ah[4], al[4], bh[2][4], bl[2][4];
        ldm4(ah, aHi + ka);
        ldm4(al, aLo + ka);
#pragma unroll
        for (int p = 0; p < 2; p++) {
            ldm4(bh[p], wHi + kb + p * 16 * RS);
            ldm4(bl[p], wLo + kb + p * 16 * RS);
        }
#pragma unroll
        for (int p = 0; p < 2; p++) {
            mma16816(acc[2 * p],     ah, bh[p][0], bh[p][1]);
            mma16816(acc[2 * p + 1], ah, bh[p][2], bh[p][3]);
            mma16816(acc[2 * p],     ah, bl[p][0], bl[p][1]);
            mma16816(acc[2 * p + 1], ah, bl[p][2], bl[p][3]);
            mma16816(acc[2 * p],     al, bh[p][0], bh[p][1]);
            mma16816(acc[2 * p + 1], al, bh[p][2], bh[p][3]);
        }
    }
}

#define ZERO_ACC(acc) do {                                                    \
    _Pragma("unroll") for (int _n = 0; _n < 4; _n++)                          \
    _Pragma("unroll") for (int _q = 0; _q < 4; _q++) acc[_n][_q] = 0.f;       \
} while (0)

// ---------------------------------------------------------------------------
// prep: bf16 hi/lo W^T images
// ---------------------------------------------------------------------------
__global__ void prep_weights(const float* __restrict__ eW1, const float* __restrict__ eW2,
                             const float* __restrict__ nW1, const float* __restrict__ nW2) {
    int lin = blockIdx.x * blockDim.x + threadIdx.x;
    if (lin >= 4 * 7 * 16384) return;
    int t = lin & 16383;
    int m = (lin >> 14) % 7;
    int l = lin / (7 * 16384);
    int k = t >> 7, n = t & 127;
    float v;
    switch (m) {
        case 0: v = eW1[(size_t)l * 49152 + (size_t)k * 128 + n]; break;
        case 1: v = eW1[(size_t)l * 49152 + (size_t)(k + 128) * 128 + n]; break;
        case 2: v = eW1[(size_t)l * 49152 + (size_t)(k + 256) * 128 + n]; break;
        case 3: v = eW2[(size_t)l * 16384 + (size_t)k * 128 + n]; break;
        case 4: v = nW1[(size_t)l * 32768 + (size_t)k * 128 + n]; break;
        case 5: v = nW1[(size_t)l * 32768 + (size_t)(k + 128) * 128 + n]; break;
        default: v = nW2[(size_t)l * 16384 + (size_t)k * 128 + n]; break;
    }
    __nv_bfloat16 hi = __float2bfloat16(v);
    __nv_bfloat16 lo = __float2bfloat16(v - __bfloat162float(hi));
    size_t base = (size_t)((l * 7 + m) * 2) * 16384;
    g_wimg[base + (size_t)n * 128 + k] = hi;            // W^T[n][k]
    g_wimg[base + 16384 + (size_t)n * 128 + k] = lo;
}

// ---------------------------------------------------------------------------
// init xw kernel (layer 0 only): XA = x @ eW1a + eb1, XB = x @ eW1b; zero agg.
// ---------------------------------------------------------------------------
__global__ __launch_bounds__(512, 2) void xw_kernel(const float* __restrict__ x,
                                                    const float* __restrict__ eb1) {
    extern __shared__ char smraw[];
    SmemT& sm = *reinterpret_cast<SmemT*>(smraw);
    const int tid = threadIdx.x, lane = tid & 31, wid = tid >> 5;
    const int wm = wid & 3, wn = wid >> 2;
    const int n0 = blockIdx.x * TM;
    char* Ahi = (char*)sm.Atiles;
    char* Alo = Ahi + TM * RS;
    const uint32_t uWhi = smem_u32(sm.W_hi), uWlo = smem_u32(sm.W_lo);

    copy_w(0, 0, uWhi, uWlo, tid);
    for (int i = tid; i < TM * 32; i += 512) {
        int r = i >> 5, c4 = i & 31;
        size_t n = (size_t)min(n0 + r, NN - 1);
        store_quad(Ahi, Alo, r, c4 * 4, *(const float4*)(x + n * 128 + c4 * 4));
    }
    for (int i = tid; i < TM * 32; i += 512) {
        int r = i >> 5, c4 = i & 31;
        int n = n0 + r;
        if (n < NN)
            *(float4*)(g_agg + (size_t)n * 128 + c4 * 4) = make_float4(0.f, 0.f, 0.f, 0.f);
    }
    CP_COMMIT_WAIT();
    __syncthreads();

    const uint32_t uAhi = smem_u32(Ahi), uAlo = smem_u32(Alo);
    const int g = lane >> 2, t = lane & 3;

    float acc[4][4];
    ZERO_ACC(acc);
    gemm_bf16x3(acc, uAhi, uAlo, uWhi, uWlo, lane, wm, wn);
#pragma unroll
    for (int h = 0; h < 2; h++) {
        int row = wm * 16 + h * 8 + g;
        int n = n0 + row;
        if (n < NN) {
#pragma unroll
            for (int nn = 0; nn < 4; nn++) {
                int col = wn * 32 + nn * 8 + t * 2;
                *(float2*)(g_XA + (size_t)n * 128 + col) =
                    make_float2(acc[nn][h * 2] + __ldg(eb1 + col),
                                acc[nn][h * 2 + 1] + __ldg(eb1 + col + 1));
            }
        }
    }
    __syncthreads();

    copy_w(0, 1, uWhi, uWlo, tid);
    CP_COMMIT_WAIT();
    __syncthreads();
    ZERO_ACC(acc);
    gemm_bf16x3(acc, uAhi, uAlo, uWhi, uWlo, lane, wm, wn);
#pragma unroll
    for (int h = 0; h < 2; h++) {
        int row = wm * 16 + h * 8 + g;
        int n = n0 + row;
        if (n < NN) {
#pragma unroll
            for (int nn = 0; nn < 4; nn++) {
                int col = wn * 32 + nn * 8 + t * 2;
                *(float2*)(g_XB + (size_t)n * 128 + col) =
                    make_float2(acc[nn][h * 2], acc[nn][h * 2 + 1]);
            }
        }
    }
}

// ---------------------------------------------------------------------------
// edge kernel (64 edges per CTA)
// ---------------------------------------------------------------------------
__global__ __launch_bounds__(512, 2) void edge_kernel(
    const int* __restrict__ ei, float* __restrict__ ea,
    const float* __restrict__ b2,
    const float* __restrict__ G, const float* __restrict__ Bv, int layer)
{
    extern __shared__ char smraw[];
    SmemT& sm = *reinterpret_cast<SmemT*>(smraw);
    const int tid = threadIdx.x, lane = tid & 31, wid = tid >> 5;
    const int wm = wid & 3, wn = wid >> 2;
    const int e0 = blockIdx.x * TM;
    char* Ahi = (char*)sm.Atiles;
    char* Alo = Ahi + TM * RS;
    const uint32_t uWhi = smem_u32(sm.W_hi), uWlo = smem_u32(sm.W_lo);

    if (tid < TM) {
        int e = min(e0 + tid, EE - 1);
        sm.idx0[tid] = ei[e];
        sm.idx1[tid] = ei[EE + e];
    }
    copy_w(layer, 2, uWhi, uWlo, tid);   // eW1c
    for (int i = tid; i < TM * 32; i += 512) {
        int r = i >> 5, c4 = i & 31;
        size_t e = (size_t)min(e0 + r, EE - 1);
        store_quad(Ahi, Alo, r, c4 * 4, *(const float4*)(ea + e * 128 + c4 * 4));
    }
    CP_COMMIT_WAIT();
    __syncthreads();

    const uint32_t uAhi = smem_u32(Ahi), uAlo = smem_u32(Alo);
    const int g = lane >> 2, t = lane & 3;

    float acc[4][4];
    ZERO_ACC(acc);
    gemm_bf16x3(acc, uAhi, uAlo, uWhi, uWlo, lane, wm, wn);
    __syncthreads();   // all reads of A & W1c done

    // prefetch eW2 NOW -- overlaps with gather-heavy epilogue1
    copy_w(layer, 3, uWhi, uWlo, tid);

    // epilogue1: h1 = relu(P + XA[dst] + XB[src]) -> split into A  (b1 folded into XA)
#pragma unroll
    for (int h = 0; h < 2; h++) {
        int row = wm * 16 + h * 8 + g;
        const float* xa = g_XA + (size_t)sm.idx1[row] * 128;
        const float* xb = g_XB + (size_t)sm.idx0[row] * 128;
#pragma unroll
        for (int nn = 0; nn < 4; nn++) {
            int col = wn * 32 + nn * 8 + t * 2;
            float2 a2 = *(const float2*)(xa + col);
            float2 b2v = *(const float2*)(xb + col);
            float u0 = fmaxf(acc[nn][h * 2]     + a2.x + b2v.x, 0.f);
            float u1 = fmaxf(acc[nn][h * 2 + 1] + a2.y + b2v.y, 0.f);
            store_pair(Ahi, Alo, row, col, u0, u1);
        }
    }
    CP_COMMIT_WAIT();
    __syncthreads();

    ZERO_ACC(acc);
    gemm_bf16x3(acc, uAhi, uAlo, uWhi, uWlo, lane, wm, wn);

    // epilogue2: LN stats
#pragma unroll
    for (int h = 0; h < 2; h++) {
        int row = wm * 16 + h * 8 + g;
        float s = 0.f, s2 = 0.f;
#pragma unroll
        for (int nn = 0; nn < 4; nn++) {
            int col = wn * 32 + nn * 8 + t * 2;
            float v0 = acc[nn][h * 2]     + __ldg(b2 + col);
            float v1 = acc[nn][h * 2 + 1] + __ldg(b2 + col + 1);
            s += v0 + v1; s2 += v0 * v0 + v1 * v1;
        }
#pragma unroll
        for (int o = 1; o < 4; o <<= 1) {
            s  += __shfl_xor_sync(0xffffffffu, s, o);
            s2 += __shfl_xor_sync(0xffffffffu, s2, o);
        }
        if (t == 0) { sm.part_s[row][wn] = s; sm.part_s2[row][wn] = s2; }
    }
    __syncthreads();   // also guards OT-vs-A union

    // LN output -> OT
#pragma unroll
    for (int h = 0; h < 2; h++) {
        int row = wm * 16 + h * 8 + g;
        float S = sm.part_s[row][0] + sm.part_s[row][1]
                + sm.part_s[row][2] + sm.part_s[row][3];
        float S2 = sm.part_s2[row][0] + sm.part_s2[row][1]
                 + sm.part_s2[row][2] + sm.part_s2[row][3];
        float mean = S * (1.f / 128);
        float var = S2 * (1.f / 128) - mean * mean;
        float inv = rsqrtf(var + LN_EPS);
#pragma unroll
        for (int nn = 0; nn < 4; nn++) {
            int col = wn * 32 + nn * 8 + t * 2;
            float v0 = acc[nn][h * 2]     + __ldg(b2 + col);
            float v1 = acc[nn][h * 2 + 1] + __ldg(b2 + col + 1);
            float l0 = (v0 - mean) * inv * __ldg(G + col)     + __ldg(Bv + col);
            float l1 = (v1 - mean) * inv * __ldg(G + col + 1) + __ldg(Bv + col + 1);
            *(float2*)(&sm.OT[row * 132 + col]) = make_float2(l0, l1);
        }
    }
    __syncthreads();

    // cooperative: ea_new = ea + LN; scatter-add float4 atomics
    for (int i = tid; i < TM * 32; i += 512) {
        int r = i >> 5, c4 = i & 31;
        int e = e0 + r;
        if (e < EE) {
            float4 o = *(float4*)(&sm.OT[r * 132 + c4 * 4]);
            float4 cur = *(const float4*)(ea + (size_t)e * 128 + c4 * 4);
            o.x += cur.x; o.y += cur.y; o.z += cur.z; o.w += cur.w;
            *(float4*)(ea + (size_t)e * 128 + c4 * 4) = o;
            atomicAdd((float4*)(g_agg + (size_t)sm.idx0[r] * 128 + c4 * 4), o);
        }
    }
}

// ---------------------------------------------------------------------------
// node kernel (64 nodes per CTA) + fused next-layer xw
// ---------------------------------------------------------------------------
__global__ __launch_bounds__(512, 2) void node_kernel(
    float* __restrict__ x,
    const float* __restrict__ b1, const float* __restrict__ b2,
    const float* __restrict__ G, const float* __restrict__ Bv,
    const float* __restrict__ eb1_next, int layer, int do_next)
{
    extern __shared__ char smraw[];
    SmemT& sm = *reinterpret_cast<SmemT*>(smraw);
    const int tid = threadIdx.x, lane = tid & 31, wid = tid >> 5;
    const int wm = wid & 3, wn = wid >> 2;
    const int n0 = blockIdx.x * TM;
    char* Ahi = (char*)sm.Atiles;
    char* Alo = Ahi + TM * RS;
    const uint32_t uWhi = smem_u32(sm.W_hi), uWlo = smem_u32(sm.W_lo);

    copy_w(layer, 4, uWhi, uWlo, tid);   // nW1a
    for (int i = tid; i < TM * 32; i += 512) {
        int r = i >> 5, c4 = i & 31;
        size_t n = (size_t)min(n0 + r, NN - 1);
        store_quad(Ahi, Alo, r, c4 * 4, *(const float4*)(x + n * 128 + c4 * 4));
    }
    CP_COMMIT_WAIT();
    __syncthreads();

    const uint32_t uAhi = smem_u32(Ahi), uAlo = smem_u32(Alo);
    const int g = lane >> 2, t = lane & 3;

    float acc[4][4];
    ZERO_ACC(acc);
    gemm_bf16x3(acc, uAhi, uAlo, uWhi, uWlo, lane, wm, wn);
    __syncthreads();

    // A <- agg, W <- nW1b; accumulate
    copy_w(layer, 5, uWhi, uWlo, tid);
    for (int i = tid; i < TM * 32; i += 512) {
        int r = i >> 5, c4 = i & 31;
        size_t n = (size_t)min(n0 + r, NN - 1);
        store_quad(Ahi, Alo, r, c4 * 4, *(const float4*)(g_agg + n * 128 + c4 * 4));
    }
    CP_COMMIT_WAIT();
    __syncthreads();
    gemm_bf16x3(acc, uAhi, uAlo, uWhi, uWlo, lane, wm, wn);
    __syncthreads();

    // relu(acc + b1) -> A; W <- nW2
    copy_w(layer, 6, uWhi, uWlo, tid);
#pragma unroll
    for (int h = 0; h < 2; h++) {
        int row = wm * 16 + h * 8 + g;
#pragma unroll
        for (int nn = 0; nn < 4; nn++) {
            int col = wn * 32 + nn * 8 + t * 2;
            float u0 = fmaxf(acc[nn][h * 2]     + __ldg(b1 + col), 0.f);
            float u1 = fmaxf(acc[nn][h * 2 + 1] + __ldg(b1 + col + 1), 0.f);
            store_pair(Ahi, Alo, row, col, u0, u1);
        }
    }
    CP_COMMIT_WAIT();
    __syncthreads();

    ZERO_ACC(acc);
    gemm_bf16x3(acc, uAhi, uAlo, uWhi, uWlo, lane, wm, wn);

    // LN stats
#pragma unroll
    for (int h = 0; h < 2; h++) {
        int row = wm * 16 + h * 8 + g;
        float s = 0.f, s2 = 0.f;
#pragma unroll
        for (int nn = 0; nn < 4; nn++) {
            int col = wn * 32 + nn * 8 + t * 2;
            float v0 = acc[nn][h * 2]     + __ldg(b2 + col);
            float v1 = acc[nn][h * 2 + 1] + __ldg(b2 + col + 1);
            s += v0 + v1; s2 += v0 * v0 + v1 * v1;
        }
#pragma unroll
        for (int o = 1; o < 4; o <<= 1) {
            s  += __shfl_xor_sync(0xffffffffu, s, o);
            s2 += __shfl_xor_sync(0xffffffffu, s2, o);
        }
        if (t == 0) { sm.part_s[row][wn] = s; sm.part_s2[row][wn] = s2; }
    }
    __syncthreads();   // all warps past GEMM3's smem reads

    // prefetch next layer's eW1a behind the LN epilogue
    if (do_next) copy_w(layer + 1, 0, uWhi, uWlo, tid);

    // x_new = x + LN; write gmem AND (if do_next) split into A for fused xw
#pragma unroll
    for (int h = 0; h < 2; h++) {
        int row = wm * 16 + h * 8 + g;
        int n = n0 + row;
        float S = sm.part_s[row][0] + sm.part_s[row][1]
                + sm.part_s[row][2] + sm.part_s[row][3];
        float S2 = sm.part_s2[row][0] + sm.part_s2[row][1]
                 + sm.part_s2[row][2] + sm.part_s2[row][3];
        float mean = S * (1.f / 128);
        float var = S2 * (1.f / 128) - mean * mean;
        float inv = rsqrtf(var + LN_EPS);
        if (n < NN) {
#pragma unroll
            for (int nn = 0; nn < 4; nn++) {
                int col = wn * 32 + nn * 8 + t * 2;
                float v0 = acc[nn][h * 2]     + __ldg(b2 + col);
                float v1 = acc[nn][h * 2 + 1] + __ldg(b2 + col + 1);
                float2 old = *(const float2*)(x + (size_t)n * 128 + col);
                float o0 = old.x + (v0 - mean) * inv * __ldg(G + col)     + __ldg(Bv + col);
                float o1 = old.y + (v1 - mean) * inv * __ldg(G + col + 1) + __ldg(Bv + col + 1);
                *(float2*)(x + (size_t)n * 128 + col) = make_float2(o0, o1);
                if (do_next) store_pair(Ahi, Alo, row, col, o0, o1);
            }
        }
    }

    if (!do_next) return;

    // zero agg rows for next layer
    for (int i = tid; i < TM * 32; i += 512) {
        int r = i >> 5, c4 = i & 31;
        int n = n0 + r;
        if (n < NN)
            *(float4*)(g_agg + (size_t)n * 128 + c4 * 4) = make_float4(0.f, 0.f, 0.f, 0.f);
    }
    CP_COMMIT_WAIT();
    __syncthreads();

    // XA = x_new @ eW1a(next) + eb1(next)
    ZERO_ACC(acc);
    gemm_bf16x3(acc, uAhi, uAlo, uWhi, uWlo, lane, wm, wn);
#pragma unroll
    for (int h = 0; h < 2; h++) {
        int row = wm * 16 + h * 8 + g;
        int n = n0 + row;
        if (n < NN) {
#pragma unroll
            for (int nn = 0; nn < 4; nn++) {
                int col = wn * 32 + nn * 8 + t * 2;
                *(float2*)(g_XA + (size_t)n * 128 + col) =
                    make_float2(acc[nn][h * 2] + __ldg(eb1_next + col),
                                acc[nn][h * 2 + 1] + __ldg(eb1_next + col + 1));
            }
        }
    }
    __syncthreads();

    // XB = x_new @ eW1b(next)
    copy_w(layer + 1, 1, uWhi, uWlo, tid);
    CP_COMMIT_WAIT();
    __syncthreads();
    ZERO_ACC(acc);
    gemm_bf16x3(acc, uAhi, uAlo, uWhi, uWlo, lane, wm, wn);
#pragma unroll
    for (int h = 0; h < 2; h++) {
        int row = wm * 16 + h * 8 + g;
        int n = n0 + row;
        if (n < NN) {
#pragma unroll
            for (int nn = 0; nn < 4; nn++) {
                int col = wn * 32 + nn * 8 + t * 2;
                *(float2*)(g_XB + (size_t)n * 128 + col) =
                    make_float2(acc[nn][h * 2], acc[nn][h * 2 + 1]);
            }
        }
    }
}

// ---------------------------------------------------------------------------
// host launcher
// ---------------------------------------------------------------------------
extern "C" void kernel_launch(void* const* d_in, const int* in_sizes, int n_in,
                              void* d_out, int out_size) {
    const float* x_in  = (const float*)d_in[0];
    const int*   ei    = (const int*)  d_in[1];
    const float* ea_in = (const float*)d_in[2];
    const float* eW1 = (const float*)d_in[3];
    const float* eb1 = (const float*)d_in[4];
    const float* eW2 = (const float*)d_in[5];
    const float* eb2 = (const float*)d_in[6];
    const float* eG  = (const float*)d_in[7];
    const float* eB  = (const float*)d_in[8];
    const float* nW1 = (const float*)d_in[9];
    const float* nb1 = (const float*)d_in[10];
    const float* nW2 = (const float*)d_in[11];
    const float* nb2 = (const float*)d_in[12];
    const float* nG  = (const float*)d_in[13];
    const float* nB  = (const float*)d_in[14];

    float* x_out  = (float*)d_out;
    float* ea_out = (float*)d_out + (size_t)NN * 128;

    const int SMEM_BYTES = (int)sizeof(SmemT);
    cudaFuncSetAttribute(xw_kernel,   cudaFuncAttributeMaxDynamicSharedMemorySize, SMEM_BYTES);
    cudaFuncSetAttribute(edge_kernel, cudaFuncAttributeMaxDynamicSharedMemorySize, SMEM_BYTES);
    cudaFuncSetAttribute(node_kernel, cudaFuncAttributeMaxDynamicSharedMemorySize, SMEM_BYTES);

    cudaMemcpyAsync(x_out,  x_in,  (size_t)NN * 128 * sizeof(float), cudaMemcpyDeviceToDevice, 0);
    cudaMemcpyAsync(ea_out, ea_in, (size_t)EE * 128 * sizeof(float), cudaMemcpyDeviceToDevice, 0);

    prep_weights<<<(4 * 7 * 16384 + 255) / 256, 256>>>(eW1, eW2, nW1, nW2);

    const int EBLK = (EE + TM - 1) / TM;   // 3907
    const int NBLK = (NN + TM - 1) / TM;   // 782

    xw_kernel<<<NBLK, 512, SMEM_BYTES>>>(x_out, eb1);

    for (int l = 0; l < LL; l++) {
        edge_kernel<<<EBLK, 512, SMEM_BYTES>>>(
            ei, ea_out,
            eb2 + (size_t)l * 128,
            eG + (size_t)l * 128,  eB + (size_t)l * 128, l);
        node_kernel<<<NBLK, 512, SMEM_BYTES>>>(
            x_out,
            nb1 + (size_t)l * 128, nb2 + (size_t)l * 128,
            nG + (size_t)l * 128,  nB + (size_t)l * 128,
            eb1 + (size_t)(l + 1 < LL ? l + 1 : l) * 128, l, l + 1 < LL ? 1 : 0);
    }
}

// round 10
// speedup vs baseline: 1.0307x; 1.0307x over previous
#include <cuda_runtime.h>
#include <cuda_bf16.h>
#include <cstdint>
#include <cstddef>

#define NN 50000
#define EE 250000
#define LL 4
#define LN_EPS 1e-5f
#define RS 272   // padded smem row stride in bytes (136 bf16)
#define TM 64    // rows per CTA tile

// ---------------------------------------------------------------------------
// device scratch
// ---------------------------------------------------------------------------
__device__ float g_agg[(size_t)NN * 128];
__device__ float g_XA[(size_t)NN * 128];   // x@eW1a + eb1
__device__ float g_XB[(size_t)NN * 128];   // x@eW1b
// weight images: [layer][mat(7)][hi/lo] each 128x128 bf16, stored as W^T[n][k]
// mats: 0=eW1a 1=eW1b 2=eW1c 3=eW2 4=nW1a 5=nW1b 6=nW2
__device__ __nv_bfloat16 g_wimg[(size_t)4 * 7 * 2 * 16384];

// ---------------------------------------------------------------------------
// shared memory  (~107 KB -> 2 CTAs/SM)
// ---------------------------------------------------------------------------
struct SmemT {
    union {
        __nv_bfloat16 Atiles[2 * TM * 136];  // A_hi then A_lo
        float OT[TM * 132];                  // staged output tile
    };
    __nv_bfloat16 W_hi[128 * 136];
    __nv_bfloat16 W_lo[128 * 136];
    float part_s[TM][4];
    float part_s2[TM][4];
    int idx0[TM];   // edge src (x_j + scatter target)
    int idx1[TM];   // edge dst (x_i)
};

// ---------------------------------------------------------------------------
// PTX helpers
// ---------------------------------------------------------------------------
__device__ __forceinline__ uint32_t smem_u32(const void* p) {
    uint32_t a;
    asm("{ .reg .u64 t; cvta.to.shared.u64 t, %1; cvt.u32.u64 %0, t; }" : "=r"(a) : "l"(p));
    return a;
}
__device__ __forceinline__ void ldm4(uint32_t r[4], uint32_t a) {
    asm volatile("ldmatrix.sync.aligned.m8n8.x4.shared.b16 {%0,%1,%2,%3}, [%4];"
        : "=r"(r[0]), "=r"(r[1]), "=r"(r[2]), "=r"(r[3]) : "r"(a));
}
__device__ __forceinline__ void mma16816(float c[4], const uint32_t a[4], uint32_t b0, uint32_t b1) {
    asm volatile("mma.sync.aligned.m16n8k16.row.col.f32.bf16.bf16.f32 "
        "{%0,%1,%2,%3},{%4,%5,%6,%7},{%8,%9},{%0,%1,%2,%3};"
        : "+f"(c[0]), "+f"(c[1]), "+f"(c[2]), "+f"(c[3])
        : "r"(a[0]), "r"(a[1]), "r"(a[2]), "r"(a[3]), "r"(b0), "r"(b1));
}
__device__ __forceinline__ void cp16(uint32_t dst, const void* src) {
    asm volatile("cp.async.cg.shared.global [%0], [%1], 16;" :: "r"(dst), "l"(src));
}
#define CP_COMMIT_WAIT() asm volatile("cp.async.commit_group;\n\tcp.async.wait_group 0;" ::: "memory")
__device__ __forceinline__ void prefetchL2(const void* p) {
    asm volatile("prefetch.global.L2 [%0];" :: "l"(p));
}

// split fp32 pair -> bf16 hi/lo (c even)
__device__ __forceinline__ void store_pair(char* hi, char* lo, int r, int c, float v0, float v1) {
    int off = r * RS + c * 2;
    __nv_bfloat16 h0 = __float2bfloat16(v0), h1 = __float2bfloat16(v1);
    __nv_bfloat16 l0 = __float2bfloat16(v0 - __bfloat162float(h0));
    __nv_bfloat16 l1 = __float2bfloat16(v1 - __bfloat162float(h1));
    *(__nv_bfloat162*)(hi + off) = __halves2bfloat162(h0, h1);
    *(__nv_bfloat162*)(lo + off) = __halves2bfloat162(l0, l1);
}

// split fp32 quad -> bf16 hi/lo as single 8B stores (c multiple of 4)
__device__ __forceinline__ void store_quad(char* hi, char* lo, int r, int c, float4 v) {
    int off = r * RS + c * 2;
    __nv_bfloat16 h0 = __float2bfloat16(v.x), h1 = __float2bfloat16(v.y);
    __nv_bfloat16 h2 = __float2bfloat16(v.z), h3 = __float2bfloat16(v.w);
    __nv_bfloat16 l0 = __float2bfloat16(v.x - __bfloat162float(h0));
    __nv_bfloat16 l1 = __float2bfloat16(v.y - __bfloat162float(h1));
    __nv_bfloat16 l2 = __float2bfloat16(v.z - __bfloat162float(h2));
    __nv_bfloat16 l3 = __float2bfloat16(v.w - __bfloat162float(h3));
    __nv_bfloat162 hp[2] = { __halves2bfloat162(h0, h1), __halves2bfloat162(h2, h3) };
    __nv_bfloat162 lp[2] = { __halves2bfloat162(l0, l1), __halves2bfloat162(l2, l3) };
    *(uint2*)(hi + off) = *(const uint2*)hp;
    *(uint2*)(lo + off) = *(const uint2*)lp;
}

// copy one hi/lo weight image pair into padded smem tiles via cp.async
__device__ __forceinline__ void copy_w(int layer, int mat, uint32_t whi, uint32_t wlo, int tid) {
    size_t base = (size_t)((layer * 7 + mat) * 2) * 16384;
    const uint4* sh = (const uint4*)(g_wimg + base);
    const uint4* sl = (const uint4*)(g_wimg + base + 16384);
    for (int i = tid; i < 2048; i += 512) {
        int row = i >> 4, q = i & 15;
        cp16(whi + row * RS + q * 16, sh + i);
        cp16(wlo + row * RS + q * 16, sl + i);
    }
}

// ---------------------------------------------------------------------------
// 64x128x128 bf16x3 GEMM, 16 warps in 4x4 grid.
// ---------------------------------------------------------------------------
__device__ __forceinline__ void gemm_bf16x3(
    float acc[4][4], uint32_t aHi, uint32_t aLo, uint32_t wHi, uint32_t wLo,
    int lane, int wm, int wn)
{
    const uint32_t aoff = (uint32_t)((wm * 16 + (lane & 15)) * RS + (lane >> 4) * 16);
    const uint32_t boff = (uint32_t)((wn * 32 + (lane & 7) + ((lane >> 4) & 1) * 8) * RS
                                     + ((lane >> 3) & 1) * 16);
#pragma unroll
    for (int ks = 0; ks < 8; ks++) {
        const uint32_t ka = aoff + ks * 32;
        const uint32_t kb = boff + ks * 32;
        uint32_t ah[4], al[4], bh[2][4], bl[2][4];
        ldm4(ah, aHi + ka);
        ldm4(al, aLo + ka);
#pragma unroll
        for (int p = 0; p < 2; p++) {
            ldm4(bh[p], wHi + kb + p * 16 * RS);
            ldm4(bl[p], wLo + kb + p * 16 * RS);
        }
#pragma unroll
        for (int p = 0; p < 2; p++) {
            mma16816(acc[2 * p],     ah, bh[p][0], bh[p][1]);
            mma16816(acc[2 * p + 1], ah, bh[p][2], bh[p][3]);
            mma16816(acc[2 * p],     ah, bl[p][0], bl[p][1]);
            mma16816(acc[2 * p + 1], ah, bl[p][2], bl[p][3]);
            mma16816(acc[2 * p],     al, bh[p][0], bh[p][1]);
            mma16816(acc[2 * p + 1], al, bh[p][2], bh[p][3]);
        }
    }
}

#define ZERO_ACC(acc) do {                                                    \
    _Pragma("unroll") for (int _n = 0; _n < 4; _n++)                          \
    _Pragma("unroll") for (int _q = 0; _q < 4; _q++) acc[_n][_q] = 0.f;       \
} while (0)

// ---------------------------------------------------------------------------
// prep: bf16 hi/lo W^T images
// ---------------------------------------------------------------------------
__global__ void prep_weights(const float* __restrict__ eW1, const float* __restrict__ eW2,
                             const float* __restrict__ nW1, const float* __restrict__ nW2) {
    int lin = blockIdx.x * blockDim.x + threadIdx.x;
    if (lin >= 4 * 7 * 16384) return;
    int t = lin & 16383;
    int m = (lin >> 14) % 7;
    int l = lin / (7 * 16384);
    int k = t >> 7, n = t & 127;
    float v;
    switch (m) {
        case 0: v = eW1[(size_t)l * 49152 + (size_t)k * 128 + n]; break;
        case 1: v = eW1[(size_t)l * 49152 + (size_t)(k + 128) * 128 + n]; break;
        case 2: v = eW1[(size_t)l * 49152 + (size_t)(k + 256) * 128 + n]; break;
        case 3: v = eW2[(size_t)l * 16384 + (size_t)k * 128 + n]; break;
        case 4: v = nW1[(size_t)l * 32768 + (size_t)k * 128 + n]; break;
        case 5: v = nW1[(size_t)l * 32768 + (size_t)(k + 128) * 128 + n]; break;
        default: v = nW2[(size_t)l * 16384 + (size_t)k * 128 + n]; break;
    }
    __nv_bfloat16 hi = __float2bfloat16(v);
    __nv_bfloat16 lo = __float2bfloat16(v - __bfloat162float(hi));
    size_t base = (size_t)((l * 7 + m) * 2) * 16384;
    g_wimg[base + (size_t)n * 128 + k] = hi;            // W^T[n][k]
    g_wimg[base + 16384 + (size_t)n * 128 + k] = lo;
}

// ---------------------------------------------------------------------------
// init xw kernel (layer 0 only): XA = x @ eW1a + eb1, XB = x @ eW1b; zero agg.
// ---------------------------------------------------------------------------
__global__ __launch_bounds__(512, 2) void xw_kernel(const float* __restrict__ x,
                                                    const float* __restrict__ eb1) {
    extern __shared__ char smraw[];
    SmemT& sm = *reinterpret_cast<SmemT*>(smraw);
    const int tid = threadIdx.x, lane = tid & 31, wid = tid >> 5;
    const int wm = wid & 3, wn = wid >> 2;
    const int n0 = blockIdx.x * TM;
    char* Ahi = (char*)sm.Atiles;
    char* Alo = Ahi + TM * RS;
    const uint32_t uWhi = smem_u32(sm.W_hi), uWlo = smem_u32(sm.W_lo);

    copy_w(0, 0, uWhi, uWlo, tid);
    for (int i = tid; i < TM * 32; i += 512) {
        int r = i >> 5, c4 = i & 31;
        size_t n = (size_t)min(n0 + r, NN - 1);
        store_quad(Ahi, Alo, r, c4 * 4, *(const float4*)(x + n * 128 + c4 * 4));
    }
    for (int i = tid; i < TM * 32; i += 512) {
        int r = i >> 5, c4 = i & 31;
        int n = n0 + r;
        if (n < NN)
            *(float4*)(g_agg + (size_t)n * 128 + c4 * 4) = make_float4(0.f, 0.f, 0.f, 0.f);
    }
    CP_COMMIT_WAIT();
    __syncthreads();

    const uint32_t uAhi = smem_u32(Ahi), uAlo = smem_u32(Alo);
    const int g = lane >> 2, t = lane & 3;

    float acc[4][4];
    ZERO_ACC(acc);
    gemm_bf16x3(acc, uAhi, uAlo, uWhi, uWlo, lane, wm, wn);
#pragma unroll
    for (int h = 0; h < 2; h++) {
        int row = wm * 16 + h * 8 + g;
        int n = n0 + row;
        if (n < NN) {
#pragma unroll
            for (int nn = 0; nn < 4; nn++) {
                int col = wn * 32 + nn * 8 + t * 2;
                *(float2*)(g_XA + (size_t)n * 128 + col) =
                    make_float2(acc[nn][h * 2] + __ldg(eb1 + col),
                                acc[nn][h * 2 + 1] + __ldg(eb1 + col + 1));
            }
        }
    }
    __syncthreads();

    copy_w(0, 1, uWhi, uWlo, tid);
    CP_COMMIT_WAIT();
    __syncthreads();
    ZERO_ACC(acc);
    gemm_bf16x3(acc, uAhi, uAlo, uWhi, uWlo, lane, wm, wn);
#pragma unroll
    for (int h = 0; h < 2; h++) {
        int row = wm * 16 + h * 8 + g;
        int n = n0 + row;
        if (n < NN) {
#pragma unroll
            for (int nn = 0; nn < 4; nn++) {
                int col = wn * 32 + nn * 8 + t * 2;
                *(float2*)(g_XB + (size_t)n * 128 + col) =
                    make_float2(acc[nn][h * 2], acc[nn][h * 2 + 1]);
            }
        }
    }
}

// ---------------------------------------------------------------------------
// edge kernel (64 edges per CTA)
// ---------------------------------------------------------------------------
__global__ __launch_bounds__(512, 2) void edge_kernel(
    const int* __restrict__ ei, float* __restrict__ ea,
    const float* __restrict__ b2,
    const float* __restrict__ G, const float* __restrict__ Bv, int layer)
{
    extern __shared__ char smraw[];
    SmemT& sm = *reinterpret_cast<SmemT*>(smraw);
    const int tid = threadIdx.x, lane = tid & 31, wid = tid >> 5;
    const int wm = wid & 3, wn = wid >> 2;
    const int e0 = blockIdx.x * TM;
    char* Ahi = (char*)sm.Atiles;
    char* Alo = Ahi + TM * RS;
    const uint32_t uWhi = smem_u32(sm.W_hi), uWlo = smem_u32(sm.W_lo);

    if (tid < TM) {
        int e = min(e0 + tid, EE - 1);
        sm.idx0[tid] = ei[e];
        sm.idx1[tid] = ei[EE + e];
    }
    copy_w(layer, 2, uWhi, uWlo, tid);   // eW1c
    for (int i = tid; i < TM * 32; i += 512) {
        int r = i >> 5, c4 = i & 31;
        size_t e = (size_t)min(e0 + r, EE - 1);
        store_quad(Ahi, Alo, r, c4 * 4, *(const float4*)(ea + e * 128 + c4 * 4));
    }
    CP_COMMIT_WAIT();
    __syncthreads();

    // L2-prefetch all gather rows for epilogue1 (lead time = GEMM1).
    // 512 threads x 1 line: r = tid>>3, li = tid&7 -> 4 lines XA row, 4 lines XB row.
    {
        int r = tid >> 3, li = tid & 7;
        if (li < 4) prefetchL2(g_XA + (size_t)sm.idx1[r] * 128 + li * 32);
        else        prefetchL2(g_XB + (size_t)sm.idx0[r] * 128 + (li - 4) * 32);
    }

    const uint32_t uAhi = smem_u32(Ahi), uAlo = smem_u32(Alo);
    const int g = lane >> 2, t = lane & 3;

    float acc[4][4];
    ZERO_ACC(acc);
    gemm_bf16x3(acc, uAhi, uAlo, uWhi, uWlo, lane, wm, wn);
    __syncthreads();   // all reads of A & W1c done

    // prefetch eW2 NOW -- overlaps with gather-heavy epilogue1
    copy_w(layer, 3, uWhi, uWlo, tid);

    // epilogue1: h1 = relu(P + XA[dst] + XB[src]) -> split into A  (b1 folded into XA)
#pragma unroll
    for (int h = 0; h < 2; h++) {
        int row = wm * 16 + h * 8 + g;
        const float* xa = g_XA + (size_t)sm.idx1[row] * 128;
        const float* xb = g_XB + (size_t)sm.idx0[row] * 128;
#pragma unroll
        for (int nn = 0; nn < 4; nn++) {
            int col = wn * 32 + nn * 8 + t * 2;
            float2 a2 = *(const float2*)(xa + col);
            float2 b2v = *(const float2*)(xb + col);
            float u0 = fmaxf(acc[nn][h * 2]     + a2.x + b2v.x, 0.f);
            float u1 = fmaxf(acc[nn][h * 2 + 1] + a2.y + b2v.y, 0.f);
            store_pair(Ahi, Alo, row, col, u0, u1);
        }
    }
    CP_COMMIT_WAIT();
    __syncthreads();

    ZERO_ACC(acc);
    gemm_bf16x3(acc, uAhi, uAlo, uWhi, uWlo, lane, wm, wn);

    // epilogue2: fold b2 into acc, compute LN stats
#pragma unroll
    for (int h = 0; h < 2; h++) {
        int row = wm * 16 + h * 8 + g;
        float s = 0.f, s2 = 0.f;
#pragma unroll
        for (int nn = 0; nn < 4; nn++) {
            int col = wn * 32 + nn * 8 + t * 2;
            acc[nn][h * 2]     += __ldg(b2 + col);
            acc[nn][h * 2 + 1] += __ldg(b2 + col + 1);
            float v0 = acc[nn][h * 2], v1 = acc[nn][h * 2 + 1];
            s += v0 + v1; s2 += v0 * v0 + v1 * v1;
        }
#pragma unroll
        for (int o = 1; o < 4; o <<= 1) {
            s  += __shfl_xor_sync(0xffffffffu, s, o);
            s2 += __shfl_xor_sync(0xffffffffu, s2, o);
        }
        if (t == 0) { sm.part_s[row][wn] = s; sm.part_s2[row][wn] = s2; }
    }
    __syncthreads();   // also guards OT-vs-A union

    // LN output -> OT (acc already holds v)
#pragma unroll
    for (int h = 0; h < 2; h++) {
        int row = wm * 16 + h * 8 + g;
        float S = sm.part_s[row][0] + sm.part_s[row][1]
                + sm.part_s[row][2] + sm.part_s[row][3];
        float S2 = sm.part_s2[row][0] + sm.part_s2[row][1]
                 + sm.part_s2[row][2] + sm.part_s2[row][3];
        float mean = S * (1.f / 128);
        float var = S2 * (1.f / 128) - mean * mean;
        float inv = rsqrtf(var + LN_EPS);
#pragma unroll
        for (int nn = 0; nn < 4; nn++) {
            int col = wn * 32 + nn * 8 + t * 2;
            float l0 = (acc[nn][h * 2]     - mean) * inv * __ldg(G + col)     + __ldg(Bv + col);
            float l1 = (acc[nn][h * 2 + 1] - mean) * inv * __ldg(G + col + 1) + __ldg(Bv + col + 1);
            *(float2*)(&sm.OT[row * 132 + col]) = make_float2(l0, l1);
        }
    }
    __syncthreads();

    // cooperative: ea_new = ea + LN; scatter-add float4 atomics
    for (int i = tid; i < TM * 32; i += 512) {
        int r = i >> 5, c4 = i & 31;
        int e = e0 + r;
        if (e < EE) {
            float4 o = *(float4*)(&sm.OT[r * 132 + c4 * 4]);
            float4 cur = *(const float4*)(ea + (size_t)e * 128 + c4 * 4);
            o.x += cur.x; o.y += cur.y; o.z += cur.z; o.w += cur.w;
            *(float4*)(ea + (size_t)e * 128 + c4 * 4) = o;
            atomicAdd((float4*)(g_agg + (size_t)sm.idx0[r] * 128 + c4 * 4), o);
        }
    }
}

// ---------------------------------------------------------------------------
// node kernel (64 nodes per CTA) + fused next-layer xw
// ---------------------------------------------------------------------------
__global__ __launch_bounds__(512, 2) void node_kernel(
    float* __restrict__ x,
    const float* __restrict__ b1, const float* __restrict__ b2,
    const float* __restrict__ G, const float* __restrict__ Bv,
    const float* __restrict__ eb1_next, int layer, int do_next)
{
    extern __shared__ char smraw[];
    SmemT& sm = *reinterpret_cast<SmemT*>(smraw);
    const int tid = threadIdx.x, lane = tid & 31, wid = tid >> 5;
    const int wm = wid & 3, wn = wid >> 2;
    const int n0 = blockIdx.x * TM;
    char* Ahi = (char*)sm.Atiles;
    char* Alo = Ahi + TM * RS;
    const uint32_t uWhi = smem_u32(sm.W_hi), uWlo = smem_u32(sm.W_lo);

    copy_w(layer, 4, uWhi, uWlo, tid);   // nW1a
    for (int i = tid; i < TM * 32; i += 512) {
        int r = i >> 5, c4 = i & 31;
        size_t n = (size_t)min(n0 + r, NN - 1);
        store_quad(Ahi, Alo, r, c4 * 4, *(const float4*)(x + n * 128 + c4 * 4));
    }
    CP_COMMIT_WAIT();
    __syncthreads();

    const uint32_t uAhi = smem_u32(Ahi), uAlo = smem_u32(Alo);
    const int g = lane >> 2, t = lane & 3;

    float acc[4][4];
    ZERO_ACC(acc);
    gemm_bf16x3(acc, uAhi, uAlo, uWhi, uWlo, lane, wm, wn);
    __syncthreads();

    // A <- agg, W <- nW1b; accumulate
    copy_w(layer, 5, uWhi, uWlo, tid);
    for (int i = tid; i < TM * 32; i += 512) {
        int r = i >> 5, c4 = i & 31;
        size_t n = (size_t)min(n0 + r, NN - 1);
        store_quad(Ahi, Alo, r, c4 * 4, *(const float4*)(g_agg + n * 128 + c4 * 4));
    }
    CP_COMMIT_WAIT();
    __syncthreads();
    gemm_bf16x3(acc, uAhi, uAlo, uWhi, uWlo, lane, wm, wn);
    __syncthreads();

    // relu(acc + b1) -> A; W <- nW2
    copy_w(layer, 6, uWhi, uWlo, tid);
#pragma unroll
    for (int h = 0; h < 2; h++) {
        int row = wm * 16 + h * 8 + g;
#pragma unroll
        for (int nn = 0; nn < 4; nn++) {
            int col = wn * 32 + nn * 8 + t * 2;
            float u0 = fmaxf(acc[nn][h * 2]     + __ldg(b1 + col), 0.f);
            float u1 = fmaxf(acc[nn][h * 2 + 1] + __ldg(b1 + col + 1), 0.f);
            store_pair(Ahi, Alo, row, col, u0, u1);
        }
    }
    CP_COMMIT_WAIT();
    __syncthreads();

    ZERO_ACC(acc);
    gemm_bf16x3(acc, uAhi, uAlo, uWhi, uWlo, lane, wm, wn);

    // LN stats (fold b2 into acc)
#pragma unroll
    for (int h = 0; h < 2; h++) {
        int row = wm * 16 + h * 8 + g;
        float s = 0.f, s2 = 0.f;
#pragma unroll
        for (int nn = 0; nn < 4; nn++) {
            int col = wn * 32 + nn * 8 + t * 2;
            acc[nn][h * 2]     += __ldg(b2 + col);
            acc[nn][h * 2 + 1] += __ldg(b2 + col + 1);
            float v0 = acc[nn][h * 2], v1 = acc[nn][h * 2 + 1];
            s += v0 + v1; s2 += v0 * v0 + v1 * v1;
        }
#pragma unroll
        for (int o = 1; o < 4; o <<= 1) {
            s  += __shfl_xor_sync(0xffffffffu, s, o);
            s2 += __shfl_xor_sync(0xffffffffu, s2, o);
        }
        if (t == 0) { sm.part_s[row][wn] = s; sm.part_s2[row][wn] = s2; }
    }
    __syncthreads();   // all warps past GEMM3's smem reads

    // prefetch next layer's eW1a behind the LN epilogue
    if (do_next) copy_w(layer + 1, 0, uWhi, uWlo, tid);

    // x_new = x + LN; write gmem AND (if do_next) split into A for fused xw
#pragma unroll
    for (int h = 0; h < 2; h++) {
        int row = wm * 16 + h * 8 + g;
        int n = n0 + row;
        float S = sm.part_s[row][0] + sm.part_s[row][1]
                + sm.part_s[row][2] + sm.part_s[row][3];
        float S2 = sm.part_s2[row][0] + sm.part_s2[row][1]
                 + sm.part_s2[row][2] + sm.part_s2[row][3];
        float mean = S * (1.f / 128);
        float var = S2 * (1.f / 128) - mean * mean;
        float inv = rsqrtf(var + LN_EPS);
        if (n < NN) {
#pragma unroll
            for (int nn = 0; nn < 4; nn++) {
                int col = wn * 32 + nn * 8 + t * 2;
                float2 old = *(const float2*)(x + (size_t)n * 128 + col);
                float o0 = old.x + (acc[nn][h * 2]     - mean) * inv * __ldg(G + col)     + __ldg(Bv + col);
                float o1 = old.y + (acc[nn][h * 2 + 1] - mean) * inv * __ldg(G + col + 1) + __ldg(Bv + col + 1);
                *(float2*)(x + (size_t)n * 128 + col) = make_float2(o0, o1);
                if (do_next) store_pair(Ahi, Alo, row, col, o0, o1);
            }
        }
    }

    if (!do_next) return;

    // zero agg rows for next layer
    for (int i = tid; i < TM * 32; i += 512) {
        int r = i >> 5, c4 = i & 31;
        int n = n0 + r;
        if (n < NN)
            *(float4*)(g_agg + (size_t)n * 128 + c4 * 4) = make_float4(0.f, 0.f, 0.f, 0.f);
    }
    CP_COMMIT_WAIT();
    __syncthreads();

    // XA = x_new @ eW1a(next) + eb1(next)
    ZERO_ACC(acc);
    gemm_bf16x3(acc, uAhi, uAlo, uWhi, uWlo, lane, wm, wn);
#pragma unroll
    for (int h = 0; h < 2; h++) {
        int row = wm * 16 + h * 8 + g;
        int n = n0 + row;
        if (n < NN) {
#pragma unroll
            for (int nn = 0; nn < 4; nn++) {
                int col = wn * 32 + nn * 8 + t * 2;
                *(float2*)(g_XA + (size_t)n * 128 + col) =
                    make_float2(acc[nn][h * 2] + __ldg(eb1_next + col),
                                acc[nn][h * 2 + 1] + __ldg(eb1_next + col + 1));
            }
        }
    }
    __syncthreads();

    // XB = x_new @ eW1b(next)
    copy_w(layer + 1, 1, uWhi, uWlo, tid);
    CP_COMMIT_WAIT();
    __syncthreads();
    ZERO_ACC(acc);
    gemm_bf16x3(acc, uAhi, uAlo, uWhi, uWlo, lane, wm, wn);
#pragma unroll
    for (int h = 0; h < 2; h++) {
        int row = wm * 16 + h * 8 + g;
        int n = n0 + row;
        if (n < NN) {
#pragma unroll
            for (int nn = 0; nn < 4; nn++) {
                int col = wn * 32 + nn * 8 + t * 2;
                *(float2*)(g_XB + (size_t)n * 128 + col) =
                    make_float2(acc[nn][h * 2], acc[nn][h * 2 + 1]);
            }
        }
    }
}

// ---------------------------------------------------------------------------
// host launcher
// ---------------------------------------------------------------------------
extern "C" void kernel_launch(void* const* d_in, const int* in_sizes, int n_in,
                              void* d_out, int out_size) {
    const float* x_in  = (const float*)d_in[0];
    const int*   ei    = (const int*)  d_in[1];
    const float* ea_in = (const float*)d_in[2];
    const float* eW1 = (const float*)d_in[3];
    const float* eb1 = (const float*)d_in[4];
    const float* eW2 = (const float*)d_in[5];
    const float* eb2 = (const float*)d_in[6];
    const float* eG  = (const float*)d_in[7];
    const float* eB  = (const float*)d_in[8];
    const float* nW1 = (const float*)d_in[9];
    const float* nb1 = (const float*)d_in[10];
    const float* nW2 = (const float*)d_in[11];
    const float* nb2 = (const float*)d_in[12];
    const float* nG  = (const float*)d_in[13];
    const float* nB  = (const float*)d_in[14];

    float* x_out  = (float*)d_out;
    float* ea_out = (float*)d_out + (size_t)NN * 128;

    const int SMEM_BYTES = (int)sizeof(SmemT);
    cudaFuncSetAttribute(xw_kernel,   cudaFuncAttributeMaxDynamicSharedMemorySize, SMEM_BYTES);
    cudaFuncSetAttribute(edge_kernel, cudaFuncAttributeMaxDynamicSharedMemorySize, SMEM_BYTES);
    cudaFuncSetAttribute(node_kernel, cudaFuncAttributeMaxDynamicSharedMemorySize, SMEM_BYTES);

    cudaMemcpyAsync(x_out,  x_in,  (size_t)NN * 128 * sizeof(float), cudaMemcpyDeviceToDevice, 0);
    cudaMemcpyAsync(ea_out, ea_in, (size_t)EE * 128 * sizeof(float), cudaMemcpyDeviceToDevice, 0);

    prep_weights<<<(4 * 7 * 16384 + 255) / 256, 256>>>(eW1, eW2, nW1, nW2);

    const int EBLK = (EE + TM - 1) / TM;   // 3907
    const int NBLK = (NN + TM - 1) / TM;   // 782

    xw_kernel<<<NBLK, 512, SMEM_BYTES>>>(x_out, eb1);

    for (int l = 0; l < LL; l++) {
        edge_kernel<<<EBLK, 512, SMEM_BYTES>>>(
            ei, ea_out,
            eb2 + (size_t)l * 128,
            eG + (size_t)l * 128,  eB + (size_t)l * 128, l);
        node_kernel<<<NBLK, 512, SMEM_BYTES>>>(
            x_out,
            nb1 + (size_t)l * 128, nb2 + (size_t)l * 128,
            nG + (size_t)l * 128,  nB + (size_t)l * 128,
            eb1 + (size_t)(l + 1 < LL ? l + 1 : l) * 128, l, l + 1 < LL ? 1 : 0);
    }
}